// round 5
// baseline (speedup 1.0000x reference)
#include <cuda_runtime.h>
#include <cuda_fp16.h>
#include <cuda_bf16.h>
#include <math.h>
#include <stdint.h>

#define S_LEN 2048
#define HIDDEN 6144
#define HD 128
#define NKVH 8
#define NG 6
#define NH 48

// bf16x3 split-K GEMM config
#define K3 (3 * HIDDEN)          // 18432
#define NCH (K3 / 32)            // 576 BK=32 chunks
#define PITCHW 20                // smem row pitch in 32-bit words (40 bf16 = 80B)
#define NSTAGE 4
#define STG_BYTES (128 * PITCHW * 4)           // 10240 per operand
#define STAGE_BYTES (2 * STG_BYTES)            // A + B
#define GEMM_SMEM (NSTAGE * STAGE_BYTES)       // 81920

typedef unsigned int u32;

// ---------------------------------------------------------------------------
// Device scratch
// ---------------------------------------------------------------------------
__device__ float g_qkv[33554432];                 // [2,2048,8,8,128] fp32
__device__ float g_ctx[25165824];                 // [2,2048,48,128]  fp32
__device__ __nv_bfloat16 g_a3x[75497472];         // [4096, 18432]
__device__ __nv_bfloat16 g_wqkv3[150994944];      // [8192, 18432]
__device__ __nv_bfloat16 g_wo3[113246208];        // [6144, 18432]
__device__ __nv_bfloat16 g_ctx3[75497472];        // [4096, 18432]

__device__ __forceinline__ u32 smem_u32(const void* p) {
    u32 a;
    asm("{ .reg .u64 t; cvta.to.shared.u64 t, %1; cvt.u32.u64 %0, t; }" : "=r"(a) : "l"(p));
    return a;
}

#define CP16(d, s) \
    asm volatile("cp.async.cg.shared.global [%0], [%1], 16;" :: "r"(d), "l"(s))
#define CP_COMMIT() asm volatile("cp.async.commit_group;")
#define CP_WAIT(n)  asm volatile("cp.async.wait_group %0;" :: "n"(n))

#define LDSM4(R, addr) \
    asm volatile("ldmatrix.sync.aligned.m8n8.x4.shared.b16 {%0,%1,%2,%3}, [%4];" \
        : "=r"((R)[0]), "=r"((R)[1]), "=r"((R)[2]), "=r"((R)[3]) : "r"(addr))
#define LDSM4T(R, addr) \
    asm volatile("ldmatrix.sync.aligned.m8n8.x4.trans.shared.b16 {%0,%1,%2,%3}, [%4];" \
        : "=r"((R)[0]), "=r"((R)[1]), "=r"((R)[2]), "=r"((R)[3]) : "r"(addr))

__device__ __forceinline__ void mma_bf16(float* c, const u32* a, const u32* b) {
    asm volatile(
        "mma.sync.aligned.m16n8k16.row.col.f32.bf16.bf16.f32 "
        "{%0,%1,%2,%3}, {%4,%5,%6,%7}, {%8,%9}, {%0,%1,%2,%3};"
        : "+f"(c[0]), "+f"(c[1]), "+f"(c[2]), "+f"(c[3])
        : "r"(a[0]), "r"(a[1]), "r"(a[2]), "r"(a[3]), "r"(b[0]), "r"(b[1]));
}
__device__ __forceinline__ void mma_f16(float* c, const u32* a, const u32* b) {
    asm volatile(
        "mma.sync.aligned.m16n8k16.row.col.f32.f16.f16.f32 "
        "{%0,%1,%2,%3}, {%4,%5,%6,%7}, {%8,%9}, {%0,%1,%2,%3};"
        : "+f"(c[0]), "+f"(c[1]), "+f"(c[2]), "+f"(c[3])
        : "r"(a[0]), "r"(a[1]), "r"(a[2]), "r"(a[3]), "r"(b[0]), "r"(b[1]));
}

// ---------------------------------------------------------------------------
// Split fp32 -> bf16 (hi, lo): [hi|hi|lo] (left operand) / [hi|lo|hi] (right)
// ---------------------------------------------------------------------------
__global__ void split3_kernel(const float* __restrict__ in,
                              __nv_bfloat16* __restrict__ out,
                              int total4, int is_right) {
    int idx = blockIdx.x * blockDim.x + threadIdx.x;
    if (idx >= total4) return;
    float4 v = ((const float4*)in)[idx];
    int r = idx / (HIDDEN / 4);
    int c = (idx % (HIDDEN / 4)) * 4;
    float vv[4] = {v.x, v.y, v.z, v.w};
    unsigned hs[4], ls[4];
#pragma unroll
    for (int j = 0; j < 4; j++) {
        __nv_bfloat16 h = __float2bfloat16(vv[j]);
        __nv_bfloat16 l = __float2bfloat16(vv[j] - __bfloat162float(h));
        hs[j] = __bfloat16_as_ushort(h);
        ls[j] = __bfloat16_as_ushort(l);
    }
    uint2 hp = make_uint2(hs[0] | (hs[1] << 16), hs[2] | (hs[3] << 16));
    uint2 lp = make_uint2(ls[0] | (ls[1] << 16), ls[2] | (ls[3] << 16));
    __nv_bfloat16* row = out + (size_t)r * K3 + c;
    *(uint2*)row = hp;
    *(uint2*)(row + HIDDEN)     = is_right ? lp : hp;
    *(uint2*)(row + 2 * HIDDEN) = is_right ? hp : lp;
}

// ---------------------------------------------------------------------------
// bf16 HMMA GEMM: 128x128 CTA tile, 4 warps (64x64 each), BK=32,
// 4-stage cp.async ring, ldmatrix frags. 128 threads, 2 CTAs/SM.
// ---------------------------------------------------------------------------
__global__ void __launch_bounds__(128, 2)
gemm_mma_kernel(const __nv_bfloat16* __restrict__ A,
                const __nv_bfloat16* __restrict__ B,
                float* __restrict__ C, int NT, int Ntot) {
    extern __shared__ __align__(16) u32 gsm[];
    const u32 gb = smem_u32(gsm);

    const int tid  = threadIdx.x;
    const int lane = tid & 31;
    const int wid  = tid >> 5;          // 0..3
    const int wm   = wid >> 1;          // 0..1
    const int wn   = wid & 1;           // 0..1

    int bid = blockIdx.x;
    int gsz = 8 * NT;
    int g = bid / gsz, r = bid % gsz;
    int mt = g * 8 + (r & 7);
    int nt = r >> 3;
    int bm = mt * 128, bn = nt * 128;

    // global load mapping: each thread owns one full 32-elem row slice (4x16B)
    const __nv_bfloat16* Ag = A + (size_t)(bm + tid) * K3;
    const __nv_bfloat16* Bg = B + (size_t)(bn + tid) * K3;
    const u32 doff = (u32)(tid * PITCHW) * 4;

    float acc[4][8][4];
#pragma unroll
    for (int mi = 0; mi < 4; mi++)
#pragma unroll
        for (int ni = 0; ni < 8; ni++)
#pragma unroll
            for (int q = 0; q < 4; q++) acc[mi][ni][q] = 0.f;

    // fragment smem addresses (stage-relative byte offsets)
    const u32 a_off = (u32)((wm * 64 + (lane & 15)) * PITCHW + 4 * (lane >> 4)) * 4;
    const u32 b_off = (u32)((wn * 64 + (lane & 7) + 8 * (lane >> 4)) * PITCHW
                            + 4 * ((lane >> 3) & 1)) * 4;

    // prologue: stages 0..2
#pragma unroll
    for (int s = 0; s < NSTAGE - 1; s++) {
        u32 sA = gb + s * STAGE_BYTES;
        u32 sB = sA + STG_BYTES;
        const __nv_bfloat16* ga = Ag + (size_t)s * 32;
        const __nv_bfloat16* gbp = Bg + (size_t)s * 32;
#pragma unroll
        for (int c16 = 0; c16 < 4; c16++) {
            CP16(sA + doff + c16 * 16, ga + c16 * 8);
            CP16(sB + doff + c16 * 16, gbp + c16 * 8);
        }
        CP_COMMIT();
    }

    for (int c = 0; c < NCH; c++) {
        CP_WAIT(2);
        __syncthreads();
        if (c + NSTAGE - 1 < NCH) {
            int s = (c + NSTAGE - 1) & (NSTAGE - 1);
            u32 sA = gb + s * STAGE_BYTES;
            u32 sB = sA + STG_BYTES;
            const __nv_bfloat16* ga = Ag + (size_t)(c + NSTAGE - 1) * 32;
            const __nv_bfloat16* gbp = Bg + (size_t)(c + NSTAGE - 1) * 32;
#pragma unroll
            for (int c16 = 0; c16 < 4; c16++) {
                CP16(sA + doff + c16 * 16, ga + c16 * 8);
                CP16(sB + doff + c16 * 16, gbp + c16 * 8);
            }
        }
        CP_COMMIT();

        u32 stA = gb + (c & (NSTAGE - 1)) * STAGE_BYTES;
        u32 stB = stA + STG_BYTES;
#pragma unroll
        for (int ks = 0; ks < 2; ks++) {
            u32 a[4][4];
#pragma unroll
            for (int mi = 0; mi < 4; mi++)
                LDSM4(a[mi], stA + a_off + mi * (16 * PITCHW * 4) + ks * 32);
#pragma unroll
            for (int nn = 0; nn < 4; nn++) {
                u32 bb[4];
                LDSM4(bb, stB + b_off + nn * (16 * PITCHW * 4) + ks * 32);
#pragma unroll
                for (int mi = 0; mi < 4; mi++) {
                    mma_bf16(acc[mi][2 * nn],     a[mi], bb);
                    mma_bf16(acc[mi][2 * nn + 1], a[mi], bb + 2);
                }
            }
        }
    }

    // epilogue
    const int lr = lane >> 2;
    const int lq = lane & 3;
#pragma unroll
    for (int mi = 0; mi < 4; mi++) {
        int row = bm + wm * 64 + mi * 16 + lr;
#pragma unroll
        for (int ni = 0; ni < 8; ni++) {
            int col = bn + wn * 64 + ni * 8 + lq * 2;
            float* p0 = C + (size_t)row * Ntot + col;
            *(float2*)p0 = make_float2(acc[mi][ni][0], acc[mi][ni][1]);
            *(float2*)(p0 + (size_t)8 * Ntot) = make_float2(acc[mi][ni][2], acc[mi][ni][3]);
        }
    }
}

// ---------------------------------------------------------------------------
// RoPE in-place on q heads (slots 0..5) and k (slot 6)
// ---------------------------------------------------------------------------
__global__ void rope_kernel(float* __restrict__ qkv) {
    int idx = blockIdx.x * blockDim.x + threadIdx.x;
    if (idx >= 4096 * 8 * 7 * 64) return;
    int i = idx & 63;
    int t = idx >> 6;
    int slot = t % 7;
    t /= 7;
    int kvh = t & 7;
    int bs = t >> 3;
    int s = bs & (S_LEN - 1);
    float inv = exp2f(-(float)i * (19.931568569324174f / 64.0f));
    float f = (float)s * inv;
    float c = cosf(f), sn = sinf(f);
    float* p = qkv + (((size_t)bs * NKVH + kvh) * 8 + slot) * HD;
    float a = p[i], b = p[i + 64];
    p[i]      = a * c - b * sn;
    p[i + 64] = b * c + a * sn;
}

// ---------------------------------------------------------------------------
// Flash attention on tensor cores, fp16 hi/lo split (3-term), causal, GQA.
// BQ=128, BK=64, 256 threads; warp w owns rows [16w,16w+16).
// ---------------------------------------------------------------------------
#define QP2 136
#define ATTN_SMEM ((128 * 2 + 64 * 4) * QP2 * 2)   // 139264 bytes

__device__ __forceinline__ u32 pack_h2(float lo, float hi) {
    u32 r;
    asm("cvt.rn.f16x2.f32 %0, %1, %2;" : "=r"(r) : "f"(hi), "f"(lo));
    return r;
}

__global__ void __launch_bounds__(256, 1)
attn_mma_kernel(const float* __restrict__ qkv, float* __restrict__ ctx) {
    extern __shared__ __align__(16) __half hsm[];
    __half* Qh = hsm;
    __half* Ql = Qh + 128 * QP2;
    __half* Kh = Ql + 128 * QP2;
    __half* Kl = Kh + 64 * QP2;
    __half* Vh = Kl + 64 * QP2;
    __half* Vl = Vh + 64 * QP2;

    const int tid  = threadIdx.x;
    const int lane = tid & 31;
    const int wid  = tid >> 5;
    const int qt   = (int)gridDim.x - 1 - blockIdx.x;   // heavy tiles first
    const int h    = blockIdx.y;
    const int b    = blockIdx.z;
    const int kvh  = h / NG, slot = h % NG;
    const int qbase = qt * 128;
    const float scale = 0.08838834764831845f;

    // --- load Q tile (scaled), split hi/lo fp16 ---
#pragma unroll
    for (int it = 0; it < 16; it++) {
        int v = tid + it * 256;
        int row = v >> 5, c4 = v & 31;
        const float* g = qkv + ((((size_t)b * S_LEN + qbase + row) * NKVH + kvh) * 8 + slot) * HD + c4 * 4;
        float4 q = *(const float4*)g;
        float f[4] = {q.x * scale, q.y * scale, q.z * scale, q.w * scale};
        __half hh[4]; float rl[4];
#pragma unroll
        for (int j = 0; j < 4; j++) {
            hh[j] = __float2half_rn(f[j]);
            rl[j] = f[j] - __half2float(hh[j]);
        }
        __half2* dh = (__half2*)&Qh[row * QP2 + c4 * 4];
        dh[0] = __halves2half2(hh[0], hh[1]);
        dh[1] = __halves2half2(hh[2], hh[3]);
        __half2* dl = (__half2*)&Ql[row * QP2 + c4 * 4];
        dl[0] = __halves2half2(__float2half_rn(rl[0]), __float2half_rn(rl[1]));
        dl[1] = __halves2half2(__float2half_rn(rl[2]), __float2half_rn(rl[3]));
    }

    float S[8][4], O[16][4];
    float m0 = -INFINITY, m1 = -INFINITY, l0 = 0.f, l1 = 0.f;
#pragma unroll
    for (int nj = 0; nj < 16; nj++)
#pragma unroll
        for (int q = 0; q < 4; q++) O[nj][q] = 0.f;

    const u32 qh_b = smem_u32(Qh), ql_b = smem_u32(Ql);
    const u32 kh_b = smem_u32(Kh), kl_b = smem_u32(Kl);
    const u32 vh_b = smem_u32(Vh), vl_b = smem_u32(Vl);
    const u32 a_off = ((u32)(wid * 16 + (lane & 15)) * QP2 + 8 * (lane >> 4)) * 2;
    const u32 b_off = ((u32)((lane & 7) + 8 * (lane >> 4)) * QP2 + 8 * ((lane >> 3) & 1)) * 2;
    const u32 v_off = ((u32)((lane & 7) + 8 * ((lane >> 3) & 1)) * QP2 + 8 * (lane >> 4)) * 2;

    const int nkt = 2 * qt + 2;
    for (int kt = 0; kt < nkt; kt++) {
        __syncthreads();
        // --- load K/V tile, split hi/lo ---
#pragma unroll
        for (int it = 0; it < 8; it++) {
            int v = tid + it * 256;
            int row = v >> 5, c4 = v & 31;
            size_t gbse = (((size_t)b * S_LEN + kt * 64 + row) * NKVH + kvh) * 8;
            float4 kk = *(const float4*)(qkv + (gbse + NG) * HD + c4 * 4);
            float4 vv = *(const float4*)(qkv + (gbse + NG + 1) * HD + c4 * 4);
            float fk[4] = {kk.x, kk.y, kk.z, kk.w};
            float fv[4] = {vv.x, vv.y, vv.z, vv.w};
            __half kh4[4], vh4[4]; float krl[4], vrl[4];
#pragma unroll
            for (int j = 0; j < 4; j++) {
                kh4[j] = __float2half_rn(fk[j]); krl[j] = fk[j] - __half2float(kh4[j]);
                vh4[j] = __float2half_rn(fv[j]); vrl[j] = fv[j] - __half2float(vh4[j]);
            }
            int so = row * QP2 + c4 * 4;
            ((__half2*)&Kh[so])[0] = __halves2half2(kh4[0], kh4[1]);
            ((__half2*)&Kh[so])[1] = __halves2half2(kh4[2], kh4[3]);
            ((__half2*)&Kl[so])[0] = __halves2half2(__float2half_rn(krl[0]), __float2half_rn(krl[1]));
            ((__half2*)&Kl[so])[1] = __halves2half2(__float2half_rn(krl[2]), __float2half_rn(krl[3]));
            ((__half2*)&Vh[so])[0] = __halves2half2(vh4[0], vh4[1]);
            ((__half2*)&Vh[so])[1] = __halves2half2(vh4[2], vh4[3]);
            ((__half2*)&Vl[so])[0] = __halves2half2(__float2half_rn(vrl[0]), __float2half_rn(vrl[1]));
            ((__half2*)&Vl[so])[1] = __halves2half2(__float2half_rn(vrl[2]), __float2half_rn(vrl[3]));
        }
        __syncthreads();

        // --- scores S = Q K^T (3-term split) ---
#pragma unroll
        for (int j = 0; j < 8; j++)
#pragma unroll
            for (int q = 0; q < 4; q++) S[j][q] = 0.f;

#pragma unroll
        for (int kc = 0; kc < 8; kc++) {
            u32 ah[4], al[4];
            LDSM4(ah, qh_b + a_off + kc * 32);
            LDSM4(al, ql_b + a_off + kc * 32);
#pragma unroll
            for (int nn = 0; nn < 4; nn++) {
                u32 bh[4], bl[4];
                u32 bo = b_off + nn * (16 * QP2 * 2) + kc * 32;
                LDSM4(bh, kh_b + bo);
                LDSM4(bl, kl_b + bo);
                mma_f16(S[2 * nn],     ah, bh);
                mma_f16(S[2 * nn],     ah, bl);
                mma_f16(S[2 * nn],     al, bh);
                mma_f16(S[2 * nn + 1], ah, bh + 2);
                mma_f16(S[2 * nn + 1], ah, bl + 2);
                mma_f16(S[2 * nn + 1], al, bh + 2);
            }
        }

        // --- causal mask (diagonal tiles only) ---
        if (kt >= 2 * qt) {
            int r0 = qbase + wid * 16 + (lane >> 2);
            int r1 = r0 + 8;
#pragma unroll
            for (int j = 0; j < 8; j++) {
                int c0 = kt * 64 + 8 * j + 2 * (lane & 3);
                if (c0 > r0)     S[j][0] = -1e30f;
                if (c0 + 1 > r0) S[j][1] = -1e30f;
                if (c0 > r1)     S[j][2] = -1e30f;
                if (c0 + 1 > r1) S[j][3] = -1e30f;
            }
        }

        // --- online softmax (rows warp-local, 4 lanes per row) ---
        float rmax0 = -INFINITY, rmax1 = -INFINITY;
#pragma unroll
        for (int j = 0; j < 8; j++) {
            rmax0 = fmaxf(rmax0, fmaxf(S[j][0], S[j][1]));
            rmax1 = fmaxf(rmax1, fmaxf(S[j][2], S[j][3]));
        }
        rmax0 = fmaxf(rmax0, __shfl_xor_sync(0xffffffffu, rmax0, 1));
        rmax0 = fmaxf(rmax0, __shfl_xor_sync(0xffffffffu, rmax0, 2));
        rmax1 = fmaxf(rmax1, __shfl_xor_sync(0xffffffffu, rmax1, 1));
        rmax1 = fmaxf(rmax1, __shfl_xor_sync(0xffffffffu, rmax1, 2));
        float mn0 = fmaxf(m0, rmax0), mn1 = fmaxf(m1, rmax1);
        float al0 = __expf(m0 - mn0), al1 = __expf(m1 - mn1);
        float rs0 = 0.f, rs1 = 0.f;
#pragma unroll
        for (int j = 0; j < 8; j++) {
            S[j][0] = __expf(S[j][0] - mn0);
            S[j][1] = __expf(S[j][1] - mn0);
            S[j][2] = __expf(S[j][2] - mn1);
            S[j][3] = __expf(S[j][3] - mn1);
            rs0 += S[j][0] + S[j][1];
            rs1 += S[j][2] + S[j][3];
        }
        rs0 += __shfl_xor_sync(0xffffffffu, rs0, 1);
        rs0 += __shfl_xor_sync(0xffffffffu, rs0, 2);
        rs1 += __shfl_xor_sync(0xffffffffu, rs1, 1);
        rs1 += __shfl_xor_sync(0xffffffffu, rs1, 2);
        l0 = l0 * al0 + rs0;
        l1 = l1 * al1 + rs1;
        m0 = mn0; m1 = mn1;
#pragma unroll
        for (int nj = 0; nj < 16; nj++) {
            O[nj][0] *= al0; O[nj][1] *= al0;
            O[nj][2] *= al1; O[nj][3] *= al1;
        }

        // --- O += P V (3-term split, P frags built in-register) ---
#pragma unroll
        for (int kc2 = 0; kc2 < 4; kc2++) {
            int j0 = 2 * kc2, j1 = 2 * kc2 + 1;
            u32 pa[4], pl[4];
            float e[4][2] = {{S[j0][0], S[j0][1]}, {S[j0][2], S[j0][3]},
                             {S[j1][0], S[j1][1]}, {S[j1][2], S[j1][3]}};
#pragma unroll
            for (int q = 0; q < 4; q++) {
                __half h0 = __float2half_rn(e[q][0]);
                __half h1 = __float2half_rn(e[q][1]);
                pa[q] = pack_h2((float)__half2float(h0), (float)__half2float(h1));
                pl[q] = pack_h2(e[q][0] - __half2float(h0), e[q][1] - __half2float(h1));
            }
#pragma unroll
            for (int nn = 0; nn < 8; nn++) {
                u32 vh[4], vl[4];
                u32 vo = v_off + kc2 * (16 * QP2 * 2) + nn * 32;
                LDSM4T(vh, vh_b + vo);
                LDSM4T(vl, vl_b + vo);
                mma_f16(O[2 * nn],     pa, vh);
                mma_f16(O[2 * nn],     pa, vl);
                mma_f16(O[2 * nn],     pl, vh);
                mma_f16(O[2 * nn + 1], pa, vh + 2);
                mma_f16(O[2 * nn + 1], pa, vl + 2);
                mma_f16(O[2 * nn + 1], pl, vh + 2);
            }
        }
    }

    // --- epilogue: normalize + write ctx[b, s, h, d] ---
    float inv0 = 1.0f / l0, inv1 = 1.0f / l1;
    int r0 = qbase + wid * 16 + (lane >> 2);
    float* d0 = ctx + ((size_t)b * S_LEN + r0) * HIDDEN + h * HD + 2 * (lane & 3);
    float* d1 = d0 + (size_t)8 * HIDDEN;
#pragma unroll
    for (int nj = 0; nj < 16; nj++) {
        *(float2*)(d0 + 8 * nj) = make_float2(O[nj][0] * inv0, O[nj][1] * inv0);
        *(float2*)(d1 + 8 * nj) = make_float2(O[nj][2] * inv1, O[nj][3] * inv1);
    }
}

// ---------------------------------------------------------------------------
extern "C" void kernel_launch(void* const* d_in, const int* in_sizes, int n_in,
                              void* d_out, int out_size) {
    const float* x    = (const float*)d_in[0];   // [2,2048,6144]
    const float* Wqkv = (const float*)d_in[1];   // [8192,6144]
    const float* Wo   = (const float*)d_in[2];   // [6144,6144]
    float* out = (float*)d_out;                  // [2,2048,6144]

    float *qkv = nullptr, *ctx = nullptr;
    __nv_bfloat16 *a3x = nullptr, *wqkv3 = nullptr, *wo3 = nullptr, *ctx3 = nullptr;
    cudaGetSymbolAddress((void**)&qkv,   g_qkv);
    cudaGetSymbolAddress((void**)&ctx,   g_ctx);
    cudaGetSymbolAddress((void**)&a3x,   g_a3x);
    cudaGetSymbolAddress((void**)&wqkv3, g_wqkv3);
    cudaGetSymbolAddress((void**)&wo3,   g_wo3);
    cudaGetSymbolAddress((void**)&ctx3,  g_ctx3);

    cudaFuncSetAttribute(gemm_mma_kernel,
                         cudaFuncAttributeMaxDynamicSharedMemorySize, GEMM_SMEM);
    cudaFuncSetAttribute(attn_mma_kernel,
                         cudaFuncAttributeMaxDynamicSharedMemorySize, ATTN_SMEM);

    // 0) bf16 hi/lo splits
    int t4x = 4096 * (HIDDEN / 4);
    int t4q = 8192 * (HIDDEN / 4);
    int t4o = 6144 * (HIDDEN / 4);
    split3_kernel<<<(t4x + 255) / 256, 256>>>(x,    a3x,   t4x, 0);
    split3_kernel<<<(t4q + 255) / 256, 256>>>(Wqkv, wqkv3, t4q, 1);
    split3_kernel<<<(t4o + 255) / 256, 256>>>(Wo,   wo3,   t4o, 1);

    // 1) QKV projection: [4096,8192]  (MT=32, NT=64)
    gemm_mma_kernel<<<32 * 64, 128, GEMM_SMEM>>>(a3x, wqkv3, qkv, 64, 8192);

    // 2) RoPE
    rope_kernel<<<(4096 * 8 * 7 * 64) / 256, 256>>>(qkv);

    // 3) Flash attention (tensor cores) -> ctx fp32
    attn_mma_kernel<<<dim3(16, NH, 2), 256, ATTN_SMEM>>>(qkv, ctx);

    // 4) split ctx, output projection: [4096,6144]  (MT=32, NT=48)
    split3_kernel<<<(t4x + 255) / 256, 256>>>(ctx, ctx3, t4x, 0);
    gemm_mma_kernel<<<32 * 48, 128, GEMM_SMEM>>>(ctx3, wo3, out, 48, 6144);
}

// round 6
// speedup vs baseline: 1.1701x; 1.1701x over previous
#include <cuda_runtime.h>
#include <cuda_fp16.h>
#include <cuda_bf16.h>
#include <math.h>
#include <stdint.h>

#define S_LEN 2048
#define HIDDEN 6144
#define HD 128
#define NKVH 8
#define NG 6
#define NH 48

// split-K GEMM config: operands stored [hi|lo] (K2 wide), 3 logical terms
#define K2 (2 * HIDDEN)          // 12288 storage width
#define NCHUNK 288               // 3 * 6144 / 64 logical K-chunks of 64
#define PITCH 72                 // bf16 per smem row (144 B)
#define ROWB 144
#define STG (128 * ROWB)         // 18432 B per operand per stage
#define STAGEB (2 * STG)
#define NST 3
#define GEMM_SMEM (NST * STAGEB) // 110592

typedef unsigned int u32;

// ---------------------------------------------------------------------------
// Device scratch
// ---------------------------------------------------------------------------
__device__ float g_qkv[33554432];                 // [2,2048,8,8,128] fp32
__device__ __nv_bfloat16 g_a2x[50331648];         // [4096, 12288]
__device__ __nv_bfloat16 g_wqkv2[100663296];      // [8192, 12288]
__device__ __nv_bfloat16 g_wo2[75497472];         // [6144, 12288]
__device__ __nv_bfloat16 g_ctx2[50331648];        // [4096, 12288]

__device__ __forceinline__ u32 smem_u32(const void* p) {
    u32 a;
    asm("{ .reg .u64 t; cvta.to.shared.u64 t, %1; cvt.u32.u64 %0, t; }" : "=r"(a) : "l"(p));
    return a;
}

#define CP16(d, s) \
    asm volatile("cp.async.cg.shared.global [%0], [%1], 16;" :: "r"(d), "l"(s))
#define CP_COMMIT() asm volatile("cp.async.commit_group;")
#define CP_WAIT(n)  asm volatile("cp.async.wait_group %0;" :: "n"(n))

#define LDSM4(R, addr) \
    asm volatile("ldmatrix.sync.aligned.m8n8.x4.shared.b16 {%0,%1,%2,%3}, [%4];" \
        : "=r"((R)[0]), "=r"((R)[1]), "=r"((R)[2]), "=r"((R)[3]) : "r"(addr))
#define LDSM4T(R, addr) \
    asm volatile("ldmatrix.sync.aligned.m8n8.x4.trans.shared.b16 {%0,%1,%2,%3}, [%4];" \
        : "=r"((R)[0]), "=r"((R)[1]), "=r"((R)[2]), "=r"((R)[3]) : "r"(addr))

__device__ __forceinline__ void mma_bf16(float* c, const u32* a, const u32* b) {
    asm volatile(
        "mma.sync.aligned.m16n8k16.row.col.f32.bf16.bf16.f32 "
        "{%0,%1,%2,%3}, {%4,%5,%6,%7}, {%8,%9}, {%0,%1,%2,%3};"
        : "+f"(c[0]), "+f"(c[1]), "+f"(c[2]), "+f"(c[3])
        : "r"(a[0]), "r"(a[1]), "r"(a[2]), "r"(a[3]), "r"(b[0]), "r"(b[1]));
}
__device__ __forceinline__ void mma_f16(float* c, const u32* a, const u32* b) {
    asm volatile(
        "mma.sync.aligned.m16n8k16.row.col.f32.f16.f16.f32 "
        "{%0,%1,%2,%3}, {%4,%5,%6,%7}, {%8,%9}, {%0,%1,%2,%3};"
        : "+f"(c[0]), "+f"(c[1]), "+f"(c[2]), "+f"(c[3])
        : "r"(a[0]), "r"(a[1]), "r"(a[2]), "r"(a[3]), "r"(b[0]), "r"(b[1]));
}

// ---------------------------------------------------------------------------
// Split fp32 -> bf16 hi/lo, stored [hi | lo] (K2 wide)
// ---------------------------------------------------------------------------
__global__ void split2_kernel(const float* __restrict__ in,
                              __nv_bfloat16* __restrict__ out, int total4) {
    int idx = blockIdx.x * blockDim.x + threadIdx.x;
    if (idx >= total4) return;
    float4 v = ((const float4*)in)[idx];
    int r = idx / (HIDDEN / 4);
    int c = (idx % (HIDDEN / 4)) * 4;
    float vv[4] = {v.x, v.y, v.z, v.w};
    unsigned hs[4], ls[4];
#pragma unroll
    for (int j = 0; j < 4; j++) {
        __nv_bfloat16 h = __float2bfloat16(vv[j]);
        __nv_bfloat16 l = __float2bfloat16(vv[j] - __bfloat162float(h));
        hs[j] = __bfloat16_as_ushort(h);
        ls[j] = __bfloat16_as_ushort(l);
    }
    __nv_bfloat16* row = out + (size_t)r * K2 + c;
    *(uint2*)row            = make_uint2(hs[0] | (hs[1] << 16), hs[2] | (hs[3] << 16));
    *(uint2*)(row + HIDDEN) = make_uint2(ls[0] | (ls[1] << 16), ls[2] | (ls[3] << 16));
}

// ---------------------------------------------------------------------------
// bf16x3 HMMA GEMM: C = A*B^T over 3 terms (ah*bh + ah*bl + al*bh).
// 128x128 CTA tile, 8 warps (64x32 each), BK=64, 3-stage cp.async ring.
// ---------------------------------------------------------------------------
__global__ void __launch_bounds__(256, 2)
gemm_mma_kernel(const __nv_bfloat16* __restrict__ A,
                const __nv_bfloat16* __restrict__ B,
                float* __restrict__ C, int NT, int Ntot) {
    extern __shared__ __align__(16) u32 gsm[];
    const u32 gb = smem_u32(gsm);

    const int tid  = threadIdx.x;
    const int lane = tid & 31;
    const int wid  = tid >> 5;
    const int wm   = wid >> 2;          // 0..1
    const int wn   = wid & 3;           // 0..3

    // 16-m super-row rasterization (squarer concurrent footprint)
    int bid = blockIdx.x;
    int srs = 16 * NT;
    int sr = bid / srs, r = bid % srs;
    int mt = sr * 16 + (r & 15);
    int nt = r >> 4;
    int bm = mt * 128, bn = nt * 128;

    // global load mapping: row = tid>>1, 64B half = tid&1 (4 x 16B chunks)
    const int lrow  = tid >> 1;
    const int lhalf = tid & 1;
    const __nv_bfloat16* Ag = A + (size_t)(bm + lrow) * K2 + lhalf * 32;
    const __nv_bfloat16* Bg = B + (size_t)(bn + lrow) * K2 + lhalf * 32;
    const u32 soff = (u32)(lrow * ROWB + lhalf * 64);

    float acc[4][4][4];
#pragma unroll
    for (int mi = 0; mi < 4; mi++)
#pragma unroll
        for (int ni = 0; ni < 4; ni++)
#pragma unroll
            for (int q = 0; q < 4; q++) acc[mi][ni][q] = 0.f;

    // ldmatrix fragment base offsets (stage-relative, bytes)
    const u32 a_off = (u32)((wm * 64 + (lane & 15)) * ROWB + (lane >> 4) * 16);
    const u32 b_off = (u32)((wn * 32 + (lane & 7) + 8 * (lane >> 4)) * ROWB
                            + ((lane >> 3) & 1) * 16);

    // chunk -> source element offset (3 logical terms over [hi|lo] storage)
    //   c <  96 : ah (c)      x bh (c)
    //   96..191 : ah (c-96)   x bl (c)        [c*64 lands in lo half]
    //   192..287: al (c-96)   x bh (c-192)
#define AOFF(c) ((size_t)(((c) < 96) ? (c) : (c) - 96) * 64)
#define BOFF(c) ((size_t)(((c) < 192) ? (c) : (c) - 192) * 64)

    // prologue: stages 0,1
#pragma unroll
    for (int s = 0; s < NST - 1; s++) {
        u32 sA = gb + s * STAGEB;
        u32 sB = sA + STG;
        const __nv_bfloat16* ga = Ag + AOFF(s);
        const __nv_bfloat16* gp = Bg + BOFF(s);
#pragma unroll
        for (int j = 0; j < 4; j++) {
            CP16(sA + soff + j * 16, ga + j * 8);
            CP16(sB + soff + j * 16, gp + j * 8);
        }
        CP_COMMIT();
    }

    int slot = 0, pslot = 2;
    for (int c = 0; c < NCHUNK; c++) {
        CP_WAIT(1);
        __syncthreads();
        if (c + 2 < NCHUNK) {
            u32 sA = gb + pslot * STAGEB;
            u32 sB = sA + STG;
            const __nv_bfloat16* ga = Ag + AOFF(c + 2);
            const __nv_bfloat16* gp = Bg + BOFF(c + 2);
#pragma unroll
            for (int j = 0; j < 4; j++) {
                CP16(sA + soff + j * 16, ga + j * 8);
                CP16(sB + soff + j * 16, gp + j * 8);
            }
        }
        CP_COMMIT();

        u32 stA = gb + slot * STAGEB;
        u32 stB = stA + STG;
#pragma unroll
        for (int ks = 0; ks < 4; ks++) {
            u32 a[4][4];
#pragma unroll
            for (int mi = 0; mi < 4; mi++)
                LDSM4(a[mi], stA + a_off + mi * (16 * ROWB) + ks * 32);
#pragma unroll
            for (int np = 0; np < 2; np++) {
                u32 bb[4];
                LDSM4(bb, stB + b_off + np * (16 * ROWB) + ks * 32);
#pragma unroll
                for (int mi = 0; mi < 4; mi++) {
                    mma_bf16(acc[mi][2 * np],     a[mi], bb);
                    mma_bf16(acc[mi][2 * np + 1], a[mi], bb + 2);
                }
            }
        }
        slot = (slot == 2) ? 0 : slot + 1;
        pslot = (pslot == 2) ? 0 : pslot + 1;
    }

    // epilogue
    const int lr = lane >> 2;
    const int lq = lane & 3;
#pragma unroll
    for (int mi = 0; mi < 4; mi++) {
        int row = bm + wm * 64 + mi * 16 + lr;
#pragma unroll
        for (int ni = 0; ni < 4; ni++) {
            int col = bn + wn * 32 + ni * 8 + lq * 2;
            float* p0 = C + (size_t)row * Ntot + col;
            *(float2*)p0 = make_float2(acc[mi][ni][0], acc[mi][ni][1]);
            *(float2*)(p0 + (size_t)8 * Ntot) = make_float2(acc[mi][ni][2], acc[mi][ni][3]);
        }
    }
}

// ---------------------------------------------------------------------------
// RoPE in-place on q heads (slots 0..5) and k (slot 6)
// ---------------------------------------------------------------------------
__global__ void rope_kernel(float* __restrict__ qkv) {
    int idx = blockIdx.x * blockDim.x + threadIdx.x;
    if (idx >= 4096 * 8 * 7 * 64) return;
    int i = idx & 63;
    int t = idx >> 6;
    int slot = t % 7;
    t /= 7;
    int kvh = t & 7;
    int bs = t >> 3;
    int s = bs & (S_LEN - 1);
    float inv = exp2f(-(float)i * (19.931568569324174f / 64.0f));
    float f = (float)s * inv;
    float c = cosf(f), sn = sinf(f);
    float* p = qkv + (((size_t)bs * NKVH + kvh) * 8 + slot) * HD;
    float a = p[i], b = p[i + 64];
    p[i]      = a * c - b * sn;
    p[i + 64] = b * c + a * sn;
}

// ---------------------------------------------------------------------------
// Flash attention on tensor cores, fp16 hi/lo split (3-term), causal, GQA.
// BQ=128, BK=64, 256 threads; epilogue writes bf16 hi/lo ctx2 directly.
// ---------------------------------------------------------------------------
#define QP2 136
#define ATTN_SMEM ((128 * 2 + 64 * 4) * QP2 * 2)   // 139264 bytes

__device__ __forceinline__ u32 pack_h2(float lo, float hi) {
    u32 r;
    asm("cvt.rn.f16x2.f32 %0, %1, %2;" : "=r"(r) : "f"(hi), "f"(lo));
    return r;
}

__global__ void __launch_bounds__(256, 1)
attn_mma_kernel(const float* __restrict__ qkv, __nv_bfloat16* __restrict__ ctx2) {
    extern __shared__ __align__(16) __half hsm[];
    __half* Qh = hsm;
    __half* Ql = Qh + 128 * QP2;
    __half* Kh = Ql + 128 * QP2;
    __half* Kl = Kh + 64 * QP2;
    __half* Vh = Kl + 64 * QP2;
    __half* Vl = Vh + 64 * QP2;

    const int tid  = threadIdx.x;
    const int lane = tid & 31;
    const int wid  = tid >> 5;
    const int qt   = (int)gridDim.x - 1 - blockIdx.x;   // heavy tiles first
    const int h    = blockIdx.y;
    const int b    = blockIdx.z;
    const int kvh  = h / NG, slot = h % NG;
    const int qbase = qt * 128;
    const float scale = 0.08838834764831845f;

    // --- load Q tile (scaled), split hi/lo fp16 ---
#pragma unroll
    for (int it = 0; it < 16; it++) {
        int v = tid + it * 256;
        int row = v >> 5, c4 = v & 31;
        const float* g = qkv + ((((size_t)b * S_LEN + qbase + row) * NKVH + kvh) * 8 + slot) * HD + c4 * 4;
        float4 q = *(const float4*)g;
        float f[4] = {q.x * scale, q.y * scale, q.z * scale, q.w * scale};
        __half hh[4]; float rl[4];
#pragma unroll
        for (int j = 0; j < 4; j++) {
            hh[j] = __float2half_rn(f[j]);
            rl[j] = f[j] - __half2float(hh[j]);
        }
        __half2* dh = (__half2*)&Qh[row * QP2 + c4 * 4];
        dh[0] = __halves2half2(hh[0], hh[1]);
        dh[1] = __halves2half2(hh[2], hh[3]);
        __half2* dl = (__half2*)&Ql[row * QP2 + c4 * 4];
        dl[0] = __halves2half2(__float2half_rn(rl[0]), __float2half_rn(rl[1]));
        dl[1] = __halves2half2(__float2half_rn(rl[2]), __float2half_rn(rl[3]));
    }

    float S[8][4], O[16][4];
    float m0 = -INFINITY, m1 = -INFINITY, l0 = 0.f, l1 = 0.f;
#pragma unroll
    for (int nj = 0; nj < 16; nj++)
#pragma unroll
        for (int q = 0; q < 4; q++) O[nj][q] = 0.f;

    const u32 qh_b = smem_u32(Qh), ql_b = smem_u32(Ql);
    const u32 kh_b = smem_u32(Kh), kl_b = smem_u32(Kl);
    const u32 vh_b = smem_u32(Vh), vl_b = smem_u32(Vl);
    const u32 a_off = ((u32)(wid * 16 + (lane & 15)) * QP2 + 8 * (lane >> 4)) * 2;
    const u32 b_off = ((u32)((lane & 7) + 8 * (lane >> 4)) * QP2 + 8 * ((lane >> 3) & 1)) * 2;
    const u32 v_off = ((u32)((lane & 7) + 8 * ((lane >> 3) & 1)) * QP2 + 8 * (lane >> 4)) * 2;

    const int nkt = 2 * qt + 2;
    for (int kt = 0; kt < nkt; kt++) {
        __syncthreads();
        // --- load K/V tile, split hi/lo ---
#pragma unroll
        for (int it = 0; it < 8; it++) {
            int v = tid + it * 256;
            int row = v >> 5, c4 = v & 31;
            size_t gbse = (((size_t)b * S_LEN + kt * 64 + row) * NKVH + kvh) * 8;
            float4 kk = *(const float4*)(qkv + (gbse + NG) * HD + c4 * 4);
            float4 vv = *(const float4*)(qkv + (gbse + NG + 1) * HD + c4 * 4);
            float fk[4] = {kk.x, kk.y, kk.z, kk.w};
            float fv[4] = {vv.x, vv.y, vv.z, vv.w};
            __half kh4[4], vh4[4]; float krl[4], vrl[4];
#pragma unroll
            for (int j = 0; j < 4; j++) {
                kh4[j] = __float2half_rn(fk[j]); krl[j] = fk[j] - __half2float(kh4[j]);
                vh4[j] = __float2half_rn(fv[j]); vrl[j] = fv[j] - __half2float(vh4[j]);
            }
            int so = row * QP2 + c4 * 4;
            ((__half2*)&Kh[so])[0] = __halves2half2(kh4[0], kh4[1]);
            ((__half2*)&Kh[so])[1] = __halves2half2(kh4[2], kh4[3]);
            ((__half2*)&Kl[so])[0] = __halves2half2(__float2half_rn(krl[0]), __float2half_rn(krl[1]));
            ((__half2*)&Kl[so])[1] = __halves2half2(__float2half_rn(krl[2]), __float2half_rn(krl[3]));
            ((__half2*)&Vh[so])[0] = __halves2half2(vh4[0], vh4[1]);
            ((__half2*)&Vh[so])[1] = __halves2half2(vh4[2], vh4[3]);
            ((__half2*)&Vl[so])[0] = __halves2half2(__float2half_rn(vrl[0]), __float2half_rn(vrl[1]));
            ((__half2*)&Vl[so])[1] = __halves2half2(__float2half_rn(vrl[2]), __float2half_rn(vrl[3]));
        }
        __syncthreads();

        // --- scores S = Q K^T (3-term split) ---
#pragma unroll
        for (int j = 0; j < 8; j++)
#pragma unroll
            for (int q = 0; q < 4; q++) S[j][q] = 0.f;

#pragma unroll
        for (int kc = 0; kc < 8; kc++) {
            u32 ah[4], al[4];
            LDSM4(ah, qh_b + a_off + kc * 32);
            LDSM4(al, ql_b + a_off + kc * 32);
#pragma unroll
            for (int nn = 0; nn < 4; nn++) {
                u32 bh[4], bl[4];
                u32 bo = b_off + nn * (16 * QP2 * 2) + kc * 32;
                LDSM4(bh, kh_b + bo);
                LDSM4(bl, kl_b + bo);
                mma_f16(S[2 * nn],     ah, bh);
                mma_f16(S[2 * nn],     ah, bl);
                mma_f16(S[2 * nn],     al, bh);
                mma_f16(S[2 * nn + 1], ah, bh + 2);
                mma_f16(S[2 * nn + 1], ah, bl + 2);
                mma_f16(S[2 * nn + 1], al, bh + 2);
            }
        }

        // --- causal mask (diagonal tiles only) ---
        if (kt >= 2 * qt) {
            int r0 = qbase + wid * 16 + (lane >> 2);
            int r1 = r0 + 8;
#pragma unroll
            for (int j = 0; j < 8; j++) {
                int c0 = kt * 64 + 8 * j + 2 * (lane & 3);
                if (c0 > r0)     S[j][0] = -1e30f;
                if (c0 + 1 > r0) S[j][1] = -1e30f;
                if (c0 > r1)     S[j][2] = -1e30f;
                if (c0 + 1 > r1) S[j][3] = -1e30f;
            }
        }

        // --- online softmax ---
        float rmax0 = -INFINITY, rmax1 = -INFINITY;
#pragma unroll
        for (int j = 0; j < 8; j++) {
            rmax0 = fmaxf(rmax0, fmaxf(S[j][0], S[j][1]));
            rmax1 = fmaxf(rmax1, fmaxf(S[j][2], S[j][3]));
        }
        rmax0 = fmaxf(rmax0, __shfl_xor_sync(0xffffffffu, rmax0, 1));
        rmax0 = fmaxf(rmax0, __shfl_xor_sync(0xffffffffu, rmax0, 2));
        rmax1 = fmaxf(rmax1, __shfl_xor_sync(0xffffffffu, rmax1, 1));
        rmax1 = fmaxf(rmax1, __shfl_xor_sync(0xffffffffu, rmax1, 2));
        float mn0 = fmaxf(m0, rmax0), mn1 = fmaxf(m1, rmax1);
        float al0 = __expf(m0 - mn0), al1 = __expf(m1 - mn1);
        float rs0 = 0.f, rs1 = 0.f;
#pragma unroll
        for (int j = 0; j < 8; j++) {
            S[j][0] = __expf(S[j][0] - mn0);
            S[j][1] = __expf(S[j][1] - mn0);
            S[j][2] = __expf(S[j][2] - mn1);
            S[j][3] = __expf(S[j][3] - mn1);
            rs0 += S[j][0] + S[j][1];
            rs1 += S[j][2] + S[j][3];
        }
        rs0 += __shfl_xor_sync(0xffffffffu, rs0, 1);
        rs0 += __shfl_xor_sync(0xffffffffu, rs0, 2);
        rs1 += __shfl_xor_sync(0xffffffffu, rs1, 1);
        rs1 += __shfl_xor_sync(0xffffffffu, rs1, 2);
        l0 = l0 * al0 + rs0;
        l1 = l1 * al1 + rs1;
        m0 = mn0; m1 = mn1;
#pragma unroll
        for (int nj = 0; nj < 16; nj++) {
            O[nj][0] *= al0; O[nj][1] *= al0;
            O[nj][2] *= al1; O[nj][3] *= al1;
        }

        // --- O += P V (3-term split, P frags in-register) ---
#pragma unroll
        for (int kc2 = 0; kc2 < 4; kc2++) {
            int j0 = 2 * kc2, j1 = 2 * kc2 + 1;
            u32 pa[4], pl[4];
            float e[4][2] = {{S[j0][0], S[j0][1]}, {S[j0][2], S[j0][3]},
                             {S[j1][0], S[j1][1]}, {S[j1][2], S[j1][3]}};
#pragma unroll
            for (int q = 0; q < 4; q++) {
                __half h0 = __float2half_rn(e[q][0]);
                __half h1 = __float2half_rn(e[q][1]);
                pa[q] = pack_h2((float)__half2float(h0), (float)__half2float(h1));
                pl[q] = pack_h2(e[q][0] - __half2float(h0), e[q][1] - __half2float(h1));
            }
#pragma unroll
            for (int nn = 0; nn < 8; nn++) {
                u32 vh[4], vl[4];
                u32 vo = v_off + kc2 * (16 * QP2 * 2) + nn * 32;
                LDSM4T(vh, vh_b + vo);
                LDSM4T(vl, vl_b + vo);
                mma_f16(O[2 * nn],     pa, vh);
                mma_f16(O[2 * nn],     pa, vl);
                mma_f16(O[2 * nn],     pl, vh);
                mma_f16(O[2 * nn + 1], pa, vh + 2);
                mma_f16(O[2 * nn + 1], pa, vl + 2);
                mma_f16(O[2 * nn + 1], pl, vh + 2);
            }
        }
    }

    // --- epilogue: normalize + write ctx2 bf16 [hi|lo] directly ---
    float inv0 = 1.0f / l0, inv1 = 1.0f / l1;
    int r0 = qbase + wid * 16 + (lane >> 2);
    __nv_bfloat16* d0 = ctx2 + ((size_t)b * S_LEN + r0) * K2 + h * HD + 2 * (lane & 3);
    __nv_bfloat16* d1 = d0 + (size_t)8 * K2;
#pragma unroll
    for (int nj = 0; nj < 16; nj++) {
        float a0 = O[nj][0] * inv0, a1 = O[nj][1] * inv0;
        float b0 = O[nj][2] * inv1, b1 = O[nj][3] * inv1;
        __nv_bfloat16 ha0 = __float2bfloat16(a0), ha1 = __float2bfloat16(a1);
        __nv_bfloat16 hb0 = __float2bfloat16(b0), hb1 = __float2bfloat16(b1);
        u32 hp0 = (u32)__bfloat16_as_ushort(ha0) | ((u32)__bfloat16_as_ushort(ha1) << 16);
        u32 hp1 = (u32)__bfloat16_as_ushort(hb0) | ((u32)__bfloat16_as_ushort(hb1) << 16);
        u32 lp0 = (u32)__bfloat16_as_ushort(__float2bfloat16(a0 - __bfloat162float(ha0)))
                | ((u32)__bfloat16_as_ushort(__float2bfloat16(a1 - __bfloat162float(ha1))) << 16);
        u32 lp1 = (u32)__bfloat16_as_ushort(__float2bfloat16(b0 - __bfloat162float(hb0)))
                | ((u32)__bfloat16_as_ushort(__float2bfloat16(b1 - __bfloat162float(hb1))) << 16);
        *(u32*)(d0 + 8 * nj)          = hp0;
        *(u32*)(d0 + HIDDEN + 8 * nj) = lp0;
        *(u32*)(d1 + 8 * nj)          = hp1;
        *(u32*)(d1 + HIDDEN + 8 * nj) = lp1;
    }
}

// ---------------------------------------------------------------------------
extern "C" void kernel_launch(void* const* d_in, const int* in_sizes, int n_in,
                              void* d_out, int out_size) {
    const float* x    = (const float*)d_in[0];   // [2,2048,6144]
    const float* Wqkv = (const float*)d_in[1];   // [8192,6144]
    const float* Wo   = (const float*)d_in[2];   // [6144,6144]
    float* out = (float*)d_out;                  // [2,2048,6144]

    float* qkv = nullptr;
    __nv_bfloat16 *a2x = nullptr, *wqkv2 = nullptr, *wo2 = nullptr, *ctx2 = nullptr;
    cudaGetSymbolAddress((void**)&qkv,   g_qkv);
    cudaGetSymbolAddress((void**)&a2x,   g_a2x);
    cudaGetSymbolAddress((void**)&wqkv2, g_wqkv2);
    cudaGetSymbolAddress((void**)&wo2,   g_wo2);
    cudaGetSymbolAddress((void**)&ctx2,  g_ctx2);

    cudaFuncSetAttribute(gemm_mma_kernel,
                         cudaFuncAttributeMaxDynamicSharedMemorySize, GEMM_SMEM);
    cudaFuncSetAttribute(attn_mma_kernel,
                         cudaFuncAttributeMaxDynamicSharedMemorySize, ATTN_SMEM);

    // 0) bf16 hi/lo splits ([hi|lo] storage)
    int t4x = 4096 * (HIDDEN / 4);
    int t4q = 8192 * (HIDDEN / 4);
    int t4o = 6144 * (HIDDEN / 4);
    split2_kernel<<<(t4x + 255) / 256, 256>>>(x,    a2x,   t4x);
    split2_kernel<<<(t4q + 255) / 256, 256>>>(Wqkv, wqkv2, t4q);
    split2_kernel<<<(t4o + 255) / 256, 256>>>(Wo,   wo2,   t4o);

    // 1) QKV projection: [4096,8192]  (MT=32, NT=64)
    gemm_mma_kernel<<<32 * 64, 256, GEMM_SMEM>>>(a2x, wqkv2, qkv, 64, 8192);

    // 2) RoPE
    rope_kernel<<<(4096 * 8 * 7 * 64) / 256, 256>>>(qkv);

    // 3) Flash attention (tensor cores) -> ctx2 bf16 hi/lo (split fused)
    attn_mma_kernel<<<dim3(16, NH, 2), 256, ATTN_SMEM>>>(qkv, ctx2);

    // 4) output projection: [4096,6144]  (MT=32, NT=48)
    gemm_mma_kernel<<<32 * 48, 256, GEMM_SMEM>>>(ctx2, wo2, out, 48, 6144);
}

// round 7
// speedup vs baseline: 1.4573x; 1.2454x over previous
#include <cuda_runtime.h>
#include <cuda_fp16.h>
#include <cuda_bf16.h>
#include <math.h>
#include <stdint.h>

#define S_LEN 2048
#define HIDDEN 6144
#define HD 128
#define NKVH 8
#define NG 6
#define NH 48

// split-K GEMM config: operands stored [hi|lo] (K2 wide), 3 logical terms
#define K2 (2 * HIDDEN)          // 12288 storage width
#define NCH 576                  // 3 * 6144 / 32 logical BK=32 chunks
#define PITCHW 20                // smem row pitch in 32-bit words (40 bf16 = 80B)
#define NSTAGE 4
#define STG_BYTES (128 * PITCHW * 4)           // 10240 per operand
#define STAGE_BYTES (2 * STG_BYTES)            // A + B
#define GEMM_SMEM (NSTAGE * STAGE_BYTES)       // 81920

typedef unsigned int u32;

// chunk -> element offset in [hi|lo] storage (3 logical terms, BK=32)
//   A: c<192 ah(c) | 192..383 ah(c-192) | 384..575 al(c-192 lands in lo half)
//   B: c<192 bh(c) | 192..383 bl(c: lands in lo half directly) | 384.. bh(c-384)
#define AOFF(c) ((size_t)(((c) < 192) ? (c) : (c) - 192) * 32)
#define BOFF(c) ((size_t)(((c) < 384) ? (c) : (c) - 384) * 32)

// ---------------------------------------------------------------------------
// Device scratch
// ---------------------------------------------------------------------------
__device__ float g_qkv[33554432];                 // [2,2048,8,8,128] fp32
__device__ __nv_bfloat16 g_a2x[50331648];         // [4096, 12288]
__device__ __nv_bfloat16 g_wqkv2[100663296];      // [8192, 12288]
__device__ __nv_bfloat16 g_wo2[75497472];         // [6144, 12288]
__device__ __nv_bfloat16 g_ctx2[50331648];        // [4096, 12288]

__device__ __forceinline__ u32 smem_u32(const void* p) {
    u32 a;
    asm("{ .reg .u64 t; cvta.to.shared.u64 t, %1; cvt.u32.u64 %0, t; }" : "=r"(a) : "l"(p));
    return a;
}

#define CP16(d, s) \
    asm volatile("cp.async.cg.shared.global [%0], [%1], 16;" :: "r"(d), "l"(s))
#define CP_COMMIT() asm volatile("cp.async.commit_group;")
#define CP_WAIT(n)  asm volatile("cp.async.wait_group %0;" :: "n"(n))

#define LDSM4(R, addr) \
    asm volatile("ldmatrix.sync.aligned.m8n8.x4.shared.b16 {%0,%1,%2,%3}, [%4];" \
        : "=r"((R)[0]), "=r"((R)[1]), "=r"((R)[2]), "=r"((R)[3]) : "r"(addr))
#define LDSM4T(R, addr) \
    asm volatile("ldmatrix.sync.aligned.m8n8.x4.trans.shared.b16 {%0,%1,%2,%3}, [%4];" \
        : "=r"((R)[0]), "=r"((R)[1]), "=r"((R)[2]), "=r"((R)[3]) : "r"(addr))

__device__ __forceinline__ void mma_bf16(float* c, const u32* a, const u32* b) {
    asm volatile(
        "mma.sync.aligned.m16n8k16.row.col.f32.bf16.bf16.f32 "
        "{%0,%1,%2,%3}, {%4,%5,%6,%7}, {%8,%9}, {%0,%1,%2,%3};"
        : "+f"(c[0]), "+f"(c[1]), "+f"(c[2]), "+f"(c[3])
        : "r"(a[0]), "r"(a[1]), "r"(a[2]), "r"(a[3]), "r"(b[0]), "r"(b[1]));
}
__device__ __forceinline__ void mma_f16(float* c, const u32* a, const u32* b) {
    asm volatile(
        "mma.sync.aligned.m16n8k16.row.col.f32.f16.f16.f32 "
        "{%0,%1,%2,%3}, {%4,%5,%6,%7}, {%8,%9}, {%0,%1,%2,%3};"
        : "+f"(c[0]), "+f"(c[1]), "+f"(c[2]), "+f"(c[3])
        : "r"(a[0]), "r"(a[1]), "r"(a[2]), "r"(a[3]), "r"(b[0]), "r"(b[1]));
}

// ---------------------------------------------------------------------------
// Split fp32 -> bf16 hi/lo, stored [hi | lo] (K2 wide)
// ---------------------------------------------------------------------------
__global__ void split2_kernel(const float* __restrict__ in,
                              __nv_bfloat16* __restrict__ out, int total4) {
    int idx = blockIdx.x * blockDim.x + threadIdx.x;
    if (idx >= total4) return;
    float4 v = ((const float4*)in)[idx];
    int r = idx / (HIDDEN / 4);
    int c = (idx % (HIDDEN / 4)) * 4;
    float vv[4] = {v.x, v.y, v.z, v.w};
    unsigned hs[4], ls[4];
#pragma unroll
    for (int j = 0; j < 4; j++) {
        __nv_bfloat16 h = __float2bfloat16(vv[j]);
        __nv_bfloat16 l = __float2bfloat16(vv[j] - __bfloat162float(h));
        hs[j] = __bfloat16_as_ushort(h);
        ls[j] = __bfloat16_as_ushort(l);
    }
    __nv_bfloat16* row = out + (size_t)r * K2 + c;
    *(uint2*)row            = make_uint2(hs[0] | (hs[1] << 16), hs[2] | (hs[3] << 16));
    *(uint2*)(row + HIDDEN) = make_uint2(ls[0] | (ls[1] << 16), ls[2] | (ls[3] << 16));
}

// ---------------------------------------------------------------------------
// bf16x3 HMMA GEMM (R4 mainloop, dedup [hi|lo] operands):
// 128x128 CTA tile, 8 warps (64x32 each), BK=32, 4-stage cp.async ring.
// ---------------------------------------------------------------------------
__global__ void __launch_bounds__(256, 2)
gemm_mma_kernel(const __nv_bfloat16* __restrict__ A,
                const __nv_bfloat16* __restrict__ B,
                float* __restrict__ C, int NT, int Ntot) {
    extern __shared__ __align__(16) u32 gsm[];
    const u32 gb = smem_u32(gsm);

    const int tid  = threadIdx.x;
    const int lane = tid & 31;
    const int wid  = tid >> 5;
    const int wm   = wid >> 2;          // 0..1
    const int wn   = wid & 3;           // 0..3

    int bid = blockIdx.x;
    int gsz = 8 * NT;
    int g = bid / gsz, r = bid % gsz;
    int mt = g * 8 + (r & 7);
    int nt = r >> 3;
    int bm = mt * 128, bn = nt * 128;

    const int grow = tid >> 2;
    const int gc16 = tid & 3;
    const __nv_bfloat16* Ag = A + (size_t)(bm + grow) * K2 + gc16 * 8;
    const __nv_bfloat16* Bg = B + (size_t)(bn + grow) * K2 + gc16 * 8;
    const u32 doff  = (u32)(grow * PITCHW + gc16 * 4) * 4;
    const u32 doff2 = doff + 64 * PITCHW * 4;

    float acc[4][4][4];
#pragma unroll
    for (int mi = 0; mi < 4; mi++)
#pragma unroll
        for (int ni = 0; ni < 4; ni++)
#pragma unroll
            for (int q = 0; q < 4; q++) acc[mi][ni][q] = 0.f;

    const u32 a_off = (u32)((wm * 64 + (lane & 15)) * PITCHW + 4 * (lane >> 4)) * 4;
    const u32 b_off = (u32)((wn * 32 + (lane & 7) + 8 * (lane >> 4)) * PITCHW
                            + 4 * ((lane >> 3) & 1)) * 4;

    // prologue: stages 0..2
#pragma unroll
    for (int s = 0; s < NSTAGE - 1; s++) {
        u32 sA = gb + s * STAGE_BYTES;
        u32 sB = sA + STG_BYTES;
        const __nv_bfloat16* ga = Ag + AOFF(s);
        const __nv_bfloat16* gp = Bg + BOFF(s);
        CP16(sA + doff,  ga);
        CP16(sA + doff2, ga + (size_t)64 * K2);
        CP16(sB + doff,  gp);
        CP16(sB + doff2, gp + (size_t)64 * K2);
        CP_COMMIT();
    }

    for (int c = 0; c < NCH; c++) {
        CP_WAIT(2);
        __syncthreads();
        if (c + NSTAGE - 1 < NCH) {
            int s = (c + NSTAGE - 1) & (NSTAGE - 1);
            u32 sA = gb + s * STAGE_BYTES;
            u32 sB = sA + STG_BYTES;
            const __nv_bfloat16* ga = Ag + AOFF(c + NSTAGE - 1);
            const __nv_bfloat16* gp = Bg + BOFF(c + NSTAGE - 1);
            CP16(sA + doff,  ga);
            CP16(sA + doff2, ga + (size_t)64 * K2);
            CP16(sB + doff,  gp);
            CP16(sB + doff2, gp + (size_t)64 * K2);
        }
        CP_COMMIT();

        u32 stA = gb + (c & (NSTAGE - 1)) * STAGE_BYTES;
        u32 stB = stA + STG_BYTES;
#pragma unroll
        for (int ks = 0; ks < 2; ks++) {
            u32 a[4][4];
#pragma unroll
            for (int mi = 0; mi < 4; mi++)
                LDSM4(a[mi], stA + a_off + mi * (16 * PITCHW * 4) + ks * 32);
#pragma unroll
            for (int np = 0; np < 2; np++) {
                u32 bb[4];
                LDSM4(bb, stB + b_off + np * (16 * PITCHW * 4) + ks * 32);
#pragma unroll
                for (int mi = 0; mi < 4; mi++) {
                    mma_bf16(acc[mi][2 * np],     a[mi], bb);
                    mma_bf16(acc[mi][2 * np + 1], a[mi], bb + 2);
                }
            }
        }
    }

    // epilogue
    const int lr = lane >> 2;
    const int lq = lane & 3;
#pragma unroll
    for (int mi = 0; mi < 4; mi++) {
        int row = bm + wm * 64 + mi * 16 + lr;
#pragma unroll
        for (int ni = 0; ni < 4; ni++) {
            int col = bn + wn * 32 + ni * 8 + lq * 2;
            float* p0 = C + (size_t)row * Ntot + col;
            *(float2*)p0 = make_float2(acc[mi][ni][0], acc[mi][ni][1]);
            *(float2*)(p0 + (size_t)8 * Ntot) = make_float2(acc[mi][ni][2], acc[mi][ni][3]);
        }
    }
}

// ---------------------------------------------------------------------------
// RoPE in-place on q heads (slots 0..5) and k (slot 6)
// ---------------------------------------------------------------------------
__global__ void rope_kernel(float* __restrict__ qkv) {
    int idx = blockIdx.x * blockDim.x + threadIdx.x;
    if (idx >= 4096 * 8 * 7 * 64) return;
    int i = idx & 63;
    int t = idx >> 6;
    int slot = t % 7;
    t /= 7;
    int kvh = t & 7;
    int bs = t >> 3;
    int s = bs & (S_LEN - 1);
    float inv = exp2f(-(float)i * (19.931568569324174f / 64.0f));
    float f = (float)s * inv;
    float c = cosf(f), sn = sinf(f);
    float* p = qkv + (((size_t)bs * NKVH + kvh) * 8 + slot) * HD;
    float a = p[i], b = p[i + 64];
    p[i]      = a * c - b * sn;
    p[i + 64] = b * c + a * sn;
}

// ---------------------------------------------------------------------------
// Flash attention on tensor cores, fp16 hi/lo split (3-term), causal, GQA.
// BQ=128, BK=64, 256 threads; epilogue writes bf16 hi/lo ctx2 directly.
// ---------------------------------------------------------------------------
#define QP2 136
#define ATTN_SMEM ((128 * 2 + 64 * 4) * QP2 * 2)   // 139264 bytes

__device__ __forceinline__ u32 pack_h2(float lo, float hi) {
    u32 r;
    asm("cvt.rn.f16x2.f32 %0, %1, %2;" : "=r"(r) : "f"(hi), "f"(lo));
    return r;
}

__global__ void __launch_bounds__(256, 1)
attn_mma_kernel(const float* __restrict__ qkv, __nv_bfloat16* __restrict__ ctx2) {
    extern __shared__ __align__(16) __half hsm[];
    __half* Qh = hsm;
    __half* Ql = Qh + 128 * QP2;
    __half* Kh = Ql + 128 * QP2;
    __half* Kl = Kh + 64 * QP2;
    __half* Vh = Kl + 64 * QP2;
    __half* Vl = Vh + 64 * QP2;

    const int tid  = threadIdx.x;
    const int lane = tid & 31;
    const int wid  = tid >> 5;
    const int qt   = (int)gridDim.x - 1 - blockIdx.x;   // heavy tiles first
    const int h    = blockIdx.y;
    const int b    = blockIdx.z;
    const int kvh  = h / NG, slot = h % NG;
    const int qbase = qt * 128;
    const float scale = 0.08838834764831845f;

    // --- load Q tile (scaled), split hi/lo fp16 ---
#pragma unroll
    for (int it = 0; it < 16; it++) {
        int v = tid + it * 256;
        int row = v >> 5, c4 = v & 31;
        const float* g = qkv + ((((size_t)b * S_LEN + qbase + row) * NKVH + kvh) * 8 + slot) * HD + c4 * 4;
        float4 q = *(const float4*)g;
        float f[4] = {q.x * scale, q.y * scale, q.z * scale, q.w * scale};
        __half hh[4]; float rl[4];
#pragma unroll
        for (int j = 0; j < 4; j++) {
            hh[j] = __float2half_rn(f[j]);
            rl[j] = f[j] - __half2float(hh[j]);
        }
        __half2* dh = (__half2*)&Qh[row * QP2 + c4 * 4];
        dh[0] = __halves2half2(hh[0], hh[1]);
        dh[1] = __halves2half2(hh[2], hh[3]);
        __half2* dl = (__half2*)&Ql[row * QP2 + c4 * 4];
        dl[0] = __halves2half2(__float2half_rn(rl[0]), __float2half_rn(rl[1]));
        dl[1] = __halves2half2(__float2half_rn(rl[2]), __float2half_rn(rl[3]));
    }

    float S[8][4], O[16][4];
    float m0 = -INFINITY, m1 = -INFINITY, l0 = 0.f, l1 = 0.f;
#pragma unroll
    for (int nj = 0; nj < 16; nj++)
#pragma unroll
        for (int q = 0; q < 4; q++) O[nj][q] = 0.f;

    const u32 qh_b = smem_u32(Qh), ql_b = smem_u32(Ql);
    const u32 kh_b = smem_u32(Kh), kl_b = smem_u32(Kl);
    const u32 vh_b = smem_u32(Vh), vl_b = smem_u32(Vl);
    const u32 a_off = ((u32)(wid * 16 + (lane & 15)) * QP2 + 8 * (lane >> 4)) * 2;
    const u32 b_off = ((u32)((lane & 7) + 8 * (lane >> 4)) * QP2 + 8 * ((lane >> 3) & 1)) * 2;
    const u32 v_off = ((u32)((lane & 7) + 8 * ((lane >> 3) & 1)) * QP2 + 8 * (lane >> 4)) * 2;

    const int nkt = 2 * qt + 2;
    for (int kt = 0; kt < nkt; kt++) {
        __syncthreads();
        // --- load K/V tile, split hi/lo ---
#pragma unroll
        for (int it = 0; it < 8; it++) {
            int v = tid + it * 256;
            int row = v >> 5, c4 = v & 31;
            size_t gbse = (((size_t)b * S_LEN + kt * 64 + row) * NKVH + kvh) * 8;
            float4 kk = *(const float4*)(qkv + (gbse + NG) * HD + c4 * 4);
            float4 vv = *(const float4*)(qkv + (gbse + NG + 1) * HD + c4 * 4);
            float fk[4] = {kk.x, kk.y, kk.z, kk.w};
            float fv[4] = {vv.x, vv.y, vv.z, vv.w};
            __half kh4[4], vh4[4]; float krl[4], vrl[4];
#pragma unroll
            for (int j = 0; j < 4; j++) {
                kh4[j] = __float2half_rn(fk[j]); krl[j] = fk[j] - __half2float(kh4[j]);
                vh4[j] = __float2half_rn(fv[j]); vrl[j] = fv[j] - __half2float(vh4[j]);
            }
            int so = row * QP2 + c4 * 4;
            ((__half2*)&Kh[so])[0] = __halves2half2(kh4[0], kh4[1]);
            ((__half2*)&Kh[so])[1] = __halves2half2(kh4[2], kh4[3]);
            ((__half2*)&Kl[so])[0] = __halves2half2(__float2half_rn(krl[0]), __float2half_rn(krl[1]));
            ((__half2*)&Kl[so])[1] = __halves2half2(__float2half_rn(krl[2]), __float2half_rn(krl[3]));
            ((__half2*)&Vh[so])[0] = __halves2half2(vh4[0], vh4[1]);
            ((__half2*)&Vh[so])[1] = __halves2half2(vh4[2], vh4[3]);
            ((__half2*)&Vl[so])[0] = __halves2half2(__float2half_rn(vrl[0]), __float2half_rn(vrl[1]));
            ((__half2*)&Vl[so])[1] = __halves2half2(__float2half_rn(vrl[2]), __float2half_rn(vrl[3]));
        }
        __syncthreads();

        // --- scores S = Q K^T (3-term split) ---
#pragma unroll
        for (int j = 0; j < 8; j++)
#pragma unroll
            for (int q = 0; q < 4; q++) S[j][q] = 0.f;

#pragma unroll
        for (int kc = 0; kc < 8; kc++) {
            u32 ah[4], al[4];
            LDSM4(ah, qh_b + a_off + kc * 32);
            LDSM4(al, ql_b + a_off + kc * 32);
#pragma unroll
            for (int nn = 0; nn < 4; nn++) {
                u32 bh[4], bl[4];
                u32 bo = b_off + nn * (16 * QP2 * 2) + kc * 32;
                LDSM4(bh, kh_b + bo);
                LDSM4(bl, kl_b + bo);
                mma_f16(S[2 * nn],     ah, bh);
                mma_f16(S[2 * nn],     ah, bl);
                mma_f16(S[2 * nn],     al, bh);
                mma_f16(S[2 * nn + 1], ah, bh + 2);
                mma_f16(S[2 * nn + 1], ah, bl + 2);
                mma_f16(S[2 * nn + 1], al, bh + 2);
            }
        }

        // --- causal mask (diagonal tiles only) ---
        if (kt >= 2 * qt) {
            int r0 = qbase + wid * 16 + (lane >> 2);
            int r1 = r0 + 8;
#pragma unroll
            for (int j = 0; j < 8; j++) {
                int c0 = kt * 64 + 8 * j + 2 * (lane & 3);
                if (c0 > r0)     S[j][0] = -1e30f;
                if (c0 + 1 > r0) S[j][1] = -1e30f;
                if (c0 > r1)     S[j][2] = -1e30f;
                if (c0 + 1 > r1) S[j][3] = -1e30f;
            }
        }

        // --- online softmax ---
        float rmax0 = -INFINITY, rmax1 = -INFINITY;
#pragma unroll
        for (int j = 0; j < 8; j++) {
            rmax0 = fmaxf(rmax0, fmaxf(S[j][0], S[j][1]));
            rmax1 = fmaxf(rmax1, fmaxf(S[j][2], S[j][3]));
        }
        rmax0 = fmaxf(rmax0, __shfl_xor_sync(0xffffffffu, rmax0, 1));
        rmax0 = fmaxf(rmax0, __shfl_xor_sync(0xffffffffu, rmax0, 2));
        rmax1 = fmaxf(rmax1, __shfl_xor_sync(0xffffffffu, rmax1, 1));
        rmax1 = fmaxf(rmax1, __shfl_xor_sync(0xffffffffu, rmax1, 2));
        float mn0 = fmaxf(m0, rmax0), mn1 = fmaxf(m1, rmax1);
        float al0 = __expf(m0 - mn0), al1 = __expf(m1 - mn1);
        float rs0 = 0.f, rs1 = 0.f;
#pragma unroll
        for (int j = 0; j < 8; j++) {
            S[j][0] = __expf(S[j][0] - mn0);
            S[j][1] = __expf(S[j][1] - mn0);
            S[j][2] = __expf(S[j][2] - mn1);
            S[j][3] = __expf(S[j][3] - mn1);
            rs0 += S[j][0] + S[j][1];
            rs1 += S[j][2] + S[j][3];
        }
        rs0 += __shfl_xor_sync(0xffffffffu, rs0, 1);
        rs0 += __shfl_xor_sync(0xffffffffu, rs0, 2);
        rs1 += __shfl_xor_sync(0xffffffffu, rs1, 1);
        rs1 += __shfl_xor_sync(0xffffffffu, rs1, 2);
        l0 = l0 * al0 + rs0;
        l1 = l1 * al1 + rs1;
        m0 = mn0; m1 = mn1;
#pragma unroll
        for (int nj = 0; nj < 16; nj++) {
            O[nj][0] *= al0; O[nj][1] *= al0;
            O[nj][2] *= al1; O[nj][3] *= al1;
        }

        // --- O += P V (3-term split, P frags in-register) ---
#pragma unroll
        for (int kc2 = 0; kc2 < 4; kc2++) {
            int j0 = 2 * kc2, j1 = 2 * kc2 + 1;
            u32 pa[4], pl[4];
            float e[4][2] = {{S[j0][0], S[j0][1]}, {S[j0][2], S[j0][3]},
                             {S[j1][0], S[j1][1]}, {S[j1][2], S[j1][3]}};
#pragma unroll
            for (int q = 0; q < 4; q++) {
                __half h0 = __float2half_rn(e[q][0]);
                __half h1 = __float2half_rn(e[q][1]);
                pa[q] = pack_h2((float)__half2float(h0), (float)__half2float(h1));
                pl[q] = pack_h2(e[q][0] - __half2float(h0), e[q][1] - __half2float(h1));
            }
#pragma unroll
            for (int nn = 0; nn < 8; nn++) {
                u32 vh[4], vl[4];
                u32 vo = v_off + kc2 * (16 * QP2 * 2) + nn * 32;
                LDSM4T(vh, vh_b + vo);
                LDSM4T(vl, vl_b + vo);
                mma_f16(O[2 * nn],     pa, vh);
                mma_f16(O[2 * nn],     pa, vl);
                mma_f16(O[2 * nn],     pl, vh);
                mma_f16(O[2 * nn + 1], pa, vh + 2);
                mma_f16(O[2 * nn + 1], pa, vl + 2);
                mma_f16(O[2 * nn + 1], pl, vh + 2);
            }
        }
    }

    // --- epilogue: normalize + write ctx2 bf16 [hi|lo] directly ---
    float inv0 = 1.0f / l0, inv1 = 1.0f / l1;
    int r0 = qbase + wid * 16 + (lane >> 2);
    __nv_bfloat16* d0 = ctx2 + ((size_t)b * S_LEN + r0) * K2 + h * HD + 2 * (lane & 3);
    __nv_bfloat16* d1 = d0 + (size_t)8 * K2;
#pragma unroll
    for (int nj = 0; nj < 16; nj++) {
        float a0 = O[nj][0] * inv0, a1 = O[nj][1] * inv0;
        float b0 = O[nj][2] * inv1, b1 = O[nj][3] * inv1;
        __nv_bfloat16 ha0 = __float2bfloat16(a0), ha1 = __float2bfloat16(a1);
        __nv_bfloat16 hb0 = __float2bfloat16(b0), hb1 = __float2bfloat16(b1);
        u32 hp0 = (u32)__bfloat16_as_ushort(ha0) | ((u32)__bfloat16_as_ushort(ha1) << 16);
        u32 hp1 = (u32)__bfloat16_as_ushort(hb0) | ((u32)__bfloat16_as_ushort(hb1) << 16);
        u32 lp0 = (u32)__bfloat16_as_ushort(__float2bfloat16(a0 - __bfloat162float(ha0)))
                | ((u32)__bfloat16_as_ushort(__float2bfloat16(a1 - __bfloat162float(ha1))) << 16);
        u32 lp1 = (u32)__bfloat16_as_ushort(__float2bfloat16(b0 - __bfloat162float(hb0)))
                | ((u32)__bfloat16_as_ushort(__float2bfloat16(b1 - __bfloat162float(hb1))) << 16);
        *(u32*)(d0 + 8 * nj)          = hp0;
        *(u32*)(d0 + HIDDEN + 8 * nj) = lp0;
        *(u32*)(d1 + 8 * nj)          = hp1;
        *(u32*)(d1 + HIDDEN + 8 * nj) = lp1;
    }
}

// ---------------------------------------------------------------------------
extern "C" void kernel_launch(void* const* d_in, const int* in_sizes, int n_in,
                              void* d_out, int out_size) {
    const float* x    = (const float*)d_in[0];   // [2,2048,6144]
    const float* Wqkv = (const float*)d_in[1];   // [8192,6144]
    const float* Wo   = (const float*)d_in[2];   // [6144,6144]
    float* out = (float*)d_out;                  // [2,2048,6144]

    float* qkv = nullptr;
    __nv_bfloat16 *a2x = nullptr, *wqkv2 = nullptr, *wo2 = nullptr, *ctx2 = nullptr;
    cudaGetSymbolAddress((void**)&qkv,   g_qkv);
    cudaGetSymbolAddress((void**)&a2x,   g_a2x);
    cudaGetSymbolAddress((void**)&wqkv2, g_wqkv2);
    cudaGetSymbolAddress((void**)&wo2,   g_wo2);
    cudaGetSymbolAddress((void**)&ctx2,  g_ctx2);

    cudaFuncSetAttribute(gemm_mma_kernel,
                         cudaFuncAttributeMaxDynamicSharedMemorySize, GEMM_SMEM);
    cudaFuncSetAttribute(attn_mma_kernel,
                         cudaFuncAttributeMaxDynamicSharedMemorySize, ATTN_SMEM);

    // 0) bf16 hi/lo splits ([hi|lo] storage)
    int t4x = 4096 * (HIDDEN / 4);
    int t4q = 8192 * (HIDDEN / 4);
    int t4o = 6144 * (HIDDEN / 4);
    split2_kernel<<<(t4x + 255) / 256, 256>>>(x,    a2x,   t4x);
    split2_kernel<<<(t4q + 255) / 256, 256>>>(Wqkv, wqkv2, t4q);
    split2_kernel<<<(t4o + 255) / 256, 256>>>(Wo,   wo2,   t4o);

    // 1) QKV projection: [4096,8192]  (MT=32, NT=64)
    gemm_mma_kernel<<<32 * 64, 256, GEMM_SMEM>>>(a2x, wqkv2, qkv, 64, 8192);

    // 2) RoPE
    rope_kernel<<<(4096 * 8 * 7 * 64) / 256, 256>>>(qkv);

    // 3) Flash attention (tensor cores) -> ctx2 bf16 hi/lo (split fused)
    attn_mma_kernel<<<dim3(16, NH, 2), 256, ATTN_SMEM>>>(qkv, ctx2);

    // 4) output projection: [4096,6144]  (MT=32, NT=48)
    gemm_mma_kernel<<<32 * 48, 256, GEMM_SMEM>>>(ctx2, wo2, out, 48, 6144);
}